// round 3
// baseline (speedup 1.0000x reference)
#include <cuda_runtime.h>

#define BATCH      16384
#define FIELD_DIM  100000
#define THREADS    256
#define WARPS      8
#define RPW        4                 // rows per warp
#define NBLOCKS    (BATCH / (WARPS * RPW))   // 512

__global__ __launch_bounds__(THREADS) void fused_kernel(
    const int*   __restrict__ x,    // [B, 26]
    const float* __restrict__ t0,   // [800000, 64]
    const float* __restrict__ t1,   // [800000, 32]
    const float* __restrict__ t2,   // [1000000, 16]
    const float* __restrict__ W1,   // [64, 32]
    const float* __restrict__ b1,   // [64]
    const float* __restrict__ W2,   // [64, 16]
    const float* __restrict__ b2,   // [64]
    float*       __restrict__ out)  // [B, 64]
{
    // sW[k*32+l] = {W[2l][k], W[2l+1][k]},  k<32 -> W1, k>=32 -> W2[k-32]
    __shared__ float2 sW[48 * 32];
    __shared__ float2 sBias[32];
    __shared__ float  sS[WARPS][RPW][48];   // per-warp block-sum staging

    const int tid = threadIdx.x;
    #pragma unroll 2
    for (int i = tid; i < 48 * 32; i += THREADS) {
        int k = i >> 5, l = i & 31;
        float a, b;
        if (k < 32) { a = W1[(2 * l) * 32 + k];        b = W1[(2 * l + 1) * 32 + k]; }
        else        { a = W2[(2 * l) * 16 + (k - 32)]; b = W2[(2 * l + 1) * 16 + (k - 32)]; }
        sW[i] = make_float2(a, b);
    }
    if (tid < 32)
        sBias[tid] = make_float2(8.f * b1[2 * tid]     + 10.f * b2[2 * tid],
                                 8.f * b1[2 * tid + 1] + 10.f * b2[2 * tid + 1]);
    __syncthreads();

    const int warp = tid >> 5;
    const int lane = tid & 31;
    const unsigned FULL = 0xffffffffu;
    const int wg = blockIdx.x * WARPS + warp;       // 0..4095
    const int row0 = wg * RPW;

    const float2 bias = sBias[lane];
    float2 acc[RPW];

    // ---- phase 1: gather + segment-sum, 4 rows sequentially ----
    #pragma unroll
    for (int r = 0; r < RPW; r++) {
        const int row = row0 + r;
        int myidx = 0;
        if (lane < 26) myidx = x[row * 26 + lane];

        // block 0: 8 fields, 256B coalesced rows
        float2 v0[8];
        #pragma unroll
        for (int f = 0; f < 8; f++) {
            int idx = __shfl_sync(FULL, myidx, f) + f * FIELD_DIM;
            v0[f] = ((const float2*)(t0 + (long long)idx * 64))[lane];
        }
        // block 1: 8 fields, 128B coalesced rows
        float v1[8];
        #pragma unroll
        for (int f = 0; f < 8; f++) {
            int idx = __shfl_sync(FULL, myidx, 8 + f) + f * FIELD_DIM;
            v1[f] = t1[(long long)idx * 32 + lane];
        }
        // block 2: 10 fields, 64B rows, two per warp-load
        const int half = lane >> 4;
        const int l16  = lane & 15;
        float v2[5];
        #pragma unroll
        for (int p = 0; p < 5; p++) {
            int f = 2 * p + half;
            int idx = __shfl_sync(FULL, myidx, 16 + f) + f * FIELD_DIM;
            v2[p] = t2[(long long)idx * 16 + l16];
        }

        float2 a = bias;
        #pragma unroll
        for (int f = 0; f < 8; f++) { a.x += v0[f].x; a.y += v0[f].y; }
        acc[r] = a;

        float s1 = 0.f;
        #pragma unroll
        for (int f = 0; f < 8; f++) s1 += v1[f];

        float s2 = 0.f;
        #pragma unroll
        for (int p = 0; p < 5; p++) s2 += v2[p];
        s2 += __shfl_xor_sync(FULL, s2, 16);

        sS[warp][r][lane] = s1;                 // 128B, 1 phase
        if (lane < 16) sS[warp][r][32 + lane] = s2;
    }
    __syncwarp();

    // ---- phase 2: projection, W loads amortized over RPW rows ----
    #pragma unroll
    for (int k4 = 0; k4 < 12; k4++) {
        float4 s4[RPW];
        #pragma unroll
        for (int r = 0; r < RPW; r++)
            s4[r] = *(const float4*)&sS[warp][r][k4 * 4];   // uniform broadcast

        #pragma unroll
        for (int j = 0; j < 4; j++) {
            float2 w = sW[(k4 * 4 + j) * 32 + lane];
            #pragma unroll
            for (int r = 0; r < RPW; r++) {
                float sv = (j == 0) ? s4[r].x : (j == 1) ? s4[r].y
                         : (j == 2) ? s4[r].z : s4[r].w;
                acc[r].x += w.x * sv;
                acc[r].y += w.y * sv;
            }
        }
    }

    #pragma unroll
    for (int r = 0; r < RPW; r++)
        ((float2*)(out + (long long)(row0 + r) * 64))[lane] = acc[r];
}

extern "C" void kernel_launch(void* const* d_in, const int* in_sizes, int n_in,
                              void* d_out, int out_size)
{
    const int*   x  = (const int*)  d_in[0];
    const float* t0 = (const float*)d_in[1];
    const float* t1 = (const float*)d_in[2];
    const float* t2 = (const float*)d_in[3];
    const float* W1 = (const float*)d_in[4];
    const float* b1 = (const float*)d_in[5];
    const float* W2 = (const float*)d_in[6];
    const float* b2 = (const float*)d_in[7];
    float* out = (float*)d_out;

    fused_kernel<<<NBLOCKS, THREADS>>>(x, t0, t1, t2, W1, b1, W2, b2, out);
}